// round 2
// baseline (speedup 1.0000x reference)
#include <cuda_runtime.h>
#include <math.h>

#define DMODEL 1024
#define NHEADS 16
#define DK 64
#define BB 2
#define SS 2048
#define NTOK (BB*SS)

// Scratch (allocation-free rule: __device__ globals). 4 x 16MB.
__device__ float g_Q[NTOK*DMODEL];   // [B*H, S, DK] head-major
__device__ float g_K[NTOK*DMODEL];   // [B*H, S, DK]
__device__ float g_V[NTOK*DMODEL];   // [B*H, S, DK]
__device__ float g_C[NTOK*DMODEL];   // [B, S, H*DK] token-major (for out-proj)

// ---------------------------------------------------------------------------
// GEMM: Y = X @ W^T + b   (X: [4096,1024], W: [1024,1024] row-major, both K-contig)
// 128x128 tile, BK=16, 256 threads, 8x8 per-thread register tile.
// ---------------------------------------------------------------------------
template<bool SPLIT>
__device__ __forceinline__ void gemm_body(const float* __restrict__ X,
                                          const float* __restrict__ W,
                                          const float* __restrict__ bias,
                                          float* __restrict__ Y)
{
    __shared__ float As[16][132];   // As[k][m]
    __shared__ float Bs[16][132];   // Bs[k][n]
    const int tid = threadIdx.x;
    const int tx = tid & 15, ty = tid >> 4;
    const int m0 = blockIdx.y * 128, n0 = blockIdx.x * 128;

    float acc[8][8];
#pragma unroll
    for (int i = 0; i < 8; i++)
#pragma unroll
        for (int j = 0; j < 8; j++) acc[i][j] = 0.f;

    for (int k0 = 0; k0 < DMODEL; k0 += 16) {
#pragma unroll
        for (int l = 0; l < 2; l++) {
            int idx = tid + l * 256;          // 0..511
            int r  = idx >> 2;                // 0..127
            int c4 = (idx & 3) * 4;           // 0,4,8,12
            float4 xa = *(const float4*)&X[(size_t)(m0 + r) * DMODEL + k0 + c4];
            As[c4+0][r] = xa.x; As[c4+1][r] = xa.y; As[c4+2][r] = xa.z; As[c4+3][r] = xa.w;
            float4 wa = *(const float4*)&W[(size_t)(n0 + r) * DMODEL + k0 + c4];
            Bs[c4+0][r] = wa.x; Bs[c4+1][r] = wa.y; Bs[c4+2][r] = wa.z; Bs[c4+3][r] = wa.w;
        }
        __syncthreads();
#pragma unroll
        for (int k = 0; k < 16; k++) {
            float a[8], b[8];
            *(float4*)&a[0] = *(const float4*)&As[k][ty*8];
            *(float4*)&a[4] = *(const float4*)&As[k][ty*8 + 4];
            *(float4*)&b[0] = *(const float4*)&Bs[k][tx*8];
            *(float4*)&b[4] = *(const float4*)&Bs[k][tx*8 + 4];
#pragma unroll
            for (int i = 0; i < 8; i++)
#pragma unroll
                for (int j = 0; j < 8; j++)
                    acc[i][j] = fmaf(a[i], b[j], acc[i][j]);
        }
        __syncthreads();
    }

    float bb[8];
#pragma unroll
    for (int j = 0; j < 8; j++) bb[j] = bias[n0 + tx*8 + j];

#pragma unroll
    for (int i = 0; i < 8; i++) {
        int m = m0 + ty*8 + i;
        float4 v0, v1;
        v0.x = acc[i][0] + bb[0]; v0.y = acc[i][1] + bb[1];
        v0.z = acc[i][2] + bb[2]; v0.w = acc[i][3] + bb[3];
        v1.x = acc[i][4] + bb[4]; v1.y = acc[i][5] + bb[5];
        v1.z = acc[i][6] + bb[6]; v1.w = acc[i][7] + bb[7];
        if (SPLIT) {
            // head-split output layout: [B*H, S, DK]
            int b = m >> 11, s = m & (SS - 1);
            int n = n0 + tx*8;
            int h = n >> 6, d = n & (DK - 1);   // tx*8..tx*8+7 stays within one head
            float* dst = &Y[(((size_t)(b * NHEADS + h)) * SS + s) * DK + d];
            *(float4*)dst = v0;
            *(float4*)(dst + 4) = v1;
        } else {
            float* dst = &Y[(size_t)m * DMODEL + n0 + tx*8];
            *(float4*)dst = v0;
            *(float4*)(dst + 4) = v1;
        }
    }
}

__global__ __launch_bounds__(256) void gemm_qkv(
    const float* __restrict__ q,  const float* __restrict__ k,  const float* __restrict__ v,
    const float* __restrict__ Wq, const float* __restrict__ Wk, const float* __restrict__ Wv,
    const float* __restrict__ bq, const float* __restrict__ bk, const float* __restrict__ bv)
{
    int z = blockIdx.z;
    const float* X    = (z == 0) ? q  : (z == 1) ? k  : v;
    const float* W    = (z == 0) ? Wq : (z == 1) ? Wk : Wv;
    const float* bias = (z == 0) ? bq : (z == 1) ? bk : bv;
    float*       Y    = (z == 0) ? g_Q : (z == 1) ? g_K : g_V;
    gemm_body<true>(X, W, bias, Y);
}

__global__ __launch_bounds__(256) void gemm_out(
    const float* __restrict__ Wo, const float* __restrict__ bo, float* __restrict__ out)
{
    gemm_body<false>(g_C, Wo, bo, out);
}

// ---------------------------------------------------------------------------
// Flash attention, fp32, causal. One CTA = 64 q rows x full d_k=64 for one (b,h).
// 256 threads as 16x16 grid, 4x4 register tiles for scores/probs and O.
// Smem: Qs^T [64][68], K^T/P shared buffer [64][68], V [64][64].
// ---------------------------------------------------------------------------
#define ATTN_SMEM ((64*68*2 + 64*64) * 4)

__global__ __launch_bounds__(256) void attn_kernel()
{
    extern __shared__ float sm[];
    float* Qs = sm;                 // Qs[d*68 + r]   (transposed)
    float* KP = sm + 64*68;         // K^T[d*68+c] then P[r*68+c]
    float* Vs = KP + 64*68;         // V[j*64 + d]

    const int tid = threadIdx.x;
    const int tx = tid & 15, ty = tid >> 4;
    const int qt = (int)gridDim.x - 1 - (int)blockIdx.x;   // heavy tiles first
    const int bh = blockIdx.y;

    const float* Qg  = g_Q + (size_t)bh * SS * DK + (size_t)qt * 64 * DK;
    const float* Kg0 = g_K + (size_t)bh * SS * DK;
    const float* Vg0 = g_V + (size_t)bh * SS * DK;

    // Load Q transposed (conflict-free store mapping: r varies across lanes)
#pragma unroll
    for (int l = 0; l < 4; l++) {
        int idx = tid + l * 256;
        int r = idx & 63, c4 = (idx >> 6) * 4;
        float4 a = *(const float4*)&Qg[r * DK + c4];
        Qs[(c4+0)*68 + r] = a.x; Qs[(c4+1)*68 + r] = a.y;
        Qs[(c4+2)*68 + r] = a.z; Qs[(c4+3)*68 + r] = a.w;
    }

    float m_run[4], l_run[4], o[4][4];
#pragma unroll
    for (int i = 0; i < 4; i++) {
        m_run[i] = -INFINITY; l_run[i] = 0.f;
#pragma unroll
        for (int j = 0; j < 4; j++) o[i][j] = 0.f;
    }

    const float scale = 0.125f;   // 1/sqrt(64)

    for (int kt = 0; kt <= qt; kt++) {
        const float* Kg = Kg0 + (size_t)kt * 64 * DK;
        const float* Vg = Vg0 + (size_t)kt * 64 * DK;

        __syncthreads();   // previous tile's P/V reads done before overwrite
#pragma unroll
        for (int l = 0; l < 4; l++) {
            int idx = tid + l * 256;
            int r = idx & 63, c4 = (idx >> 6) * 4;        // transposed K store
            float4 a = *(const float4*)&Kg[r * DK + c4];
            KP[(c4+0)*68 + r] = a.x; KP[(c4+1)*68 + r] = a.y;
            KP[(c4+2)*68 + r] = a.z; KP[(c4+3)*68 + r] = a.w;
            int r2 = idx >> 4, c42 = (idx & 15) * 4;      // direct V copy
            *(float4*)&Vs[r2 * 64 + c42] = *(const float4*)&Vg[r2 * DK + c42];
        }
        __syncthreads();

        // scores S = Q K^T (4x4 per thread)
        float s[4][4];
#pragma unroll
        for (int i = 0; i < 4; i++)
#pragma unroll
            for (int j = 0; j < 4; j++) s[i][j] = 0.f;
#pragma unroll 16
        for (int d = 0; d < 64; d++) {
            float a[4], b[4];
            *(float4*)a = *(const float4*)&Qs[d*68 + ty*4];
            *(float4*)b = *(const float4*)&KP[d*68 + tx*4];
#pragma unroll
            for (int i = 0; i < 4; i++)
#pragma unroll
                for (int j = 0; j < 4; j++)
                    s[i][j] = fmaf(a[i], b[j], s[i][j]);
        }

        if (kt == qt) {   // diagonal tile: causal mask
#pragma unroll
            for (int i = 0; i < 4; i++)
#pragma unroll
                for (int j = 0; j < 4; j++) {
                    int qi = ty*4 + i, kj = tx*4 + j;
                    s[i][j] = (kj <= qi) ? s[i][j] * scale : -INFINITY;
                }
        } else {
#pragma unroll
            for (int i = 0; i < 4; i++)
#pragma unroll
                for (int j = 0; j < 4; j++) s[i][j] *= scale;
        }

        // online softmax: row reductions across the 16-lane half-warp (same ty)
        float rmax[4];
#pragma unroll
        for (int i = 0; i < 4; i++)
            rmax[i] = fmaxf(fmaxf(s[i][0], s[i][1]), fmaxf(s[i][2], s[i][3]));
#pragma unroll
        for (int off = 8; off >= 1; off >>= 1)
#pragma unroll
            for (int i = 0; i < 4; i++)
                rmax[i] = fmaxf(rmax[i], __shfl_xor_sync(0xffffffffu, rmax[i], off));

        float corr[4], rsum[4];
#pragma unroll
        for (int i = 0; i < 4; i++) {
            float mn = fmaxf(m_run[i], rmax[i]);
            corr[i] = __expf(m_run[i] - mn);
            m_run[i] = mn;
            rsum[i] = 0.f;
        }
#pragma unroll
        for (int i = 0; i < 4; i++)
#pragma unroll
            for (int j = 0; j < 4; j++) {
                float p = __expf(s[i][j] - m_run[i]);
                s[i][j] = p;
                rsum[i] += p;
            }
#pragma unroll
        for (int off = 8; off >= 1; off >>= 1)
#pragma unroll
            for (int i = 0; i < 4; i++)
                rsum[i] += __shfl_xor_sync(0xffffffffu, rsum[i], off);
#pragma unroll
        for (int i = 0; i < 4; i++) {
            l_run[i] = l_run[i] * corr[i] + rsum[i];
#pragma unroll
            for (int j = 0; j < 4; j++) o[i][j] *= corr[i];
        }

        __syncthreads();   // everyone done reading K^T from KP
#pragma unroll
        for (int i = 0; i < 4; i++) {
            float4 pv; pv.x = s[i][0]; pv.y = s[i][1]; pv.z = s[i][2]; pv.w = s[i][3];
            *(float4*)&KP[(ty*4 + i)*68 + tx*4] = pv;
        }
        __syncthreads();

        // O += P V
#pragma unroll 16
        for (int jj = 0; jj < 64; jj++) {
            float4 b4 = *(const float4*)&Vs[jj*64 + tx*4];
            float a0 = KP[(ty*4+0)*68 + jj];
            float a1 = KP[(ty*4+1)*68 + jj];
            float a2 = KP[(ty*4+2)*68 + jj];
            float a3 = KP[(ty*4+3)*68 + jj];
            o[0][0] = fmaf(a0, b4.x, o[0][0]); o[0][1] = fmaf(a0, b4.y, o[0][1]);
            o[0][2] = fmaf(a0, b4.z, o[0][2]); o[0][3] = fmaf(a0, b4.w, o[0][3]);
            o[1][0] = fmaf(a1, b4.x, o[1][0]); o[1][1] = fmaf(a1, b4.y, o[1][1]);
            o[1][2] = fmaf(a1, b4.z, o[1][2]); o[1][3] = fmaf(a1, b4.w, o[1][3]);
            o[2][0] = fmaf(a2, b4.x, o[2][0]); o[2][1] = fmaf(a2, b4.y, o[2][1]);
            o[2][2] = fmaf(a2, b4.z, o[2][2]); o[2][3] = fmaf(a2, b4.w, o[2][3]);
            o[3][0] = fmaf(a3, b4.x, o[3][0]); o[3][1] = fmaf(a3, b4.y, o[3][1]);
            o[3][2] = fmaf(a3, b4.z, o[3][2]); o[3][3] = fmaf(a3, b4.w, o[3][3]);
        }
    }

    // epilogue: ctx written token-major [B, S, H*DK] so out-proj reads [4096,1024]
    int b = bh / NHEADS, h = bh % NHEADS;
#pragma unroll
    for (int i = 0; i < 4; i++) {
        float inv = 1.f / l_run[i];
        int srow = qt*64 + ty*4 + i;
        float4 vv;
        vv.x = o[i][0] * inv; vv.y = o[i][1] * inv;
        vv.z = o[i][2] * inv; vv.w = o[i][3] * inv;
        *(float4*)&g_C[((size_t)(b * SS + srow)) * DMODEL + h * DK + tx*4] = vv;
    }
}

// ---------------------------------------------------------------------------

extern "C" void kernel_launch(void* const* d_in, const int* in_sizes, int n_in,
                              void* d_out, int out_size)
{
    const float* q  = (const float*)d_in[0];
    const float* k  = (const float*)d_in[1];
    const float* v  = (const float*)d_in[2];
    const float* Wq = (const float*)d_in[3];
    const float* bq = (const float*)d_in[4];
    const float* Wk = (const float*)d_in[5];
    const float* bk = (const float*)d_in[6];
    const float* Wv = (const float*)d_in[7];
    const float* bv = (const float*)d_in[8];
    const float* Wo = (const float*)d_in[9];
    const float* bo = (const float*)d_in[10];
    // d_in[11] = mask (exact tril; handled as causal structure in-kernel)

    float* out = (float*)d_out;

    // 1) QKV projections (head-split layout)
    gemm_qkv<<<dim3(DMODEL/128, NTOK/128, 3), 256>>>(q, k, v, Wq, Wk, Wv, bq, bk, bv);

    // 2) Flash attention (causal)
    cudaFuncSetAttribute(attn_kernel, cudaFuncAttributeMaxDynamicSharedMemorySize, ATTN_SMEM);
    attn_kernel<<<dim3(SS/64, BB*NHEADS), 256, ATTN_SMEM>>>();

    // 3) Output projection straight into d_out
    gemm_out<<<dim3(DMODEL/128, NTOK/128), 256>>>(Wo, bo, out);
}

// round 5
// speedup vs baseline: 1.5477x; 1.5477x over previous
#include <cuda_runtime.h>
#include <cuda_bf16.h>
#include <math.h>
#include <stdint.h>

#define DMODEL 1024
#define NHEADS 16
#define DK 64
#define BB 2
#define SS 2048
#define NTOK (BB*SS)

// Scratch (allocation-free rule: __device__ globals).
__device__ float g_Q[NTOK*DMODEL];   // [B*H, S, DK] head-major
__device__ float g_K[NTOK*DMODEL];   // [B*H, S, DK]
__device__ float g_V[NTOK*DMODEL];   // [B*H, S, DK]
__device__ float g_C[NTOK*DMODEL];   // [B, S, H*DK] token-major (for out-proj)

// ===========================================================================
// Warp-level tensor core helpers (legacy mma.sync path — works on compute_103)
// ===========================================================================
__device__ __forceinline__ uint32_t smem_u32(const void* p) {
    uint32_t a;
    asm("{ .reg .u64 t; cvta.to.shared.u64 t, %1; cvt.u32.u64 %0, t; }"
        : "=r"(a) : "l"(p));
    return a;
}

__device__ __forceinline__ void ldsm_x4(uint32_t& r0, uint32_t& r1,
                                        uint32_t& r2, uint32_t& r3, uint32_t addr) {
    asm volatile("ldmatrix.sync.aligned.m8n8.x4.shared.b16 {%0,%1,%2,%3}, [%4];"
                 : "=r"(r0), "=r"(r1), "=r"(r2), "=r"(r3) : "r"(addr));
}

__device__ __forceinline__ void mma_bf16(float* c, const uint32_t* a, const uint32_t* b) {
    asm volatile(
        "mma.sync.aligned.m16n8k16.row.col.f32.bf16.bf16.f32 "
        "{%0,%1,%2,%3}, {%4,%5,%6,%7}, {%8,%9}, {%0,%1,%2,%3};"
        : "+f"(c[0]), "+f"(c[1]), "+f"(c[2]), "+f"(c[3])
        : "r"(a[0]), "r"(a[1]), "r"(a[2]), "r"(a[3]), "r"(b[0]), "r"(b[1]));
}

// split fp32 -> (hi, lo) bf16x2 packs for two consecutive values
__device__ __forceinline__ void split2(float2 v, uint32_t& hp, uint32_t& lp) {
    asm("cvt.rn.bf16x2.f32 %0, %1, %2;" : "=r"(hp) : "f"(v.y), "f"(v.x));
    float h0 = __uint_as_float(hp << 16);
    float h1 = __uint_as_float(hp & 0xffff0000u);
    asm("cvt.rn.bf16x2.f32 %0, %1, %2;" : "=r"(lp) : "f"(v.y - h1), "f"(v.x - h0));
}

// ===========================================================================
// Tensor-core GEMM: Y = X @ W^T + b  (split-bf16: hi*hi + hi*lo + lo*hi)
// CTA tile 128x128, BK=64, 256 threads (8 warps, 2m x 4n), warp tile 64x32.
// Smem: 4 x (128x64 bf16) = 64 KB, XOR swizzle (16B chunk ^ (row&7)).
// ===========================================================================
#define BKC 64
#define NCHUNK (DMODEL / BKC)        // 16
#define TILE_B (128 * BKC * 2)       // 16 KB per bf16 tile
#define GEMM_SMEM (4 * TILE_B)       // 64 KB

__device__ __forceinline__ uint32_t swz(int row, int chunk) {
    return (uint32_t)(row * 128 + ((chunk ^ (row & 7)) << 4));
}

template<bool SPLIT>
__device__ __forceinline__ void gemm_tc_body(const float* __restrict__ X,
                                             const float* __restrict__ W,
                                             const float* __restrict__ bias,
                                             float* __restrict__ Y)
{
    extern __shared__ char smc[];
    char* sAhi = smc;
    char* sAlo = smc + TILE_B;
    char* sBhi = smc + 2 * TILE_B;
    char* sBlo = smc + 3 * TILE_B;
    const uint32_t aAhi = smem_u32(sAhi), aAlo = smem_u32(sAlo);
    const uint32_t aBhi = smem_u32(sBhi), aBlo = smem_u32(sBlo);

    const int tid = threadIdx.x;
    const int wid = tid >> 5, l = tid & 31;
    const int warp_m = (wid & 1) * 64;        // 0 / 64
    const int warp_n = (wid >> 1) * 32;       // 0 / 32 / 64 / 96
    const int m0 = blockIdx.y * 128, n0 = blockIdx.x * 128;

    float c[4][4][4];
#pragma unroll
    for (int i = 0; i < 4; i++)
#pragma unroll
        for (int j = 0; j < 4; j++)
#pragma unroll
            for (int t = 0; t < 4; t++) c[i][j][t] = 0.f;

    const float* Xp = X + (size_t)m0 * DMODEL;
    const float* Wp = W + (size_t)n0 * DMODEL;

    // ldmatrix lane address components (constant across chunks)
    const int a_row_off = ((l >> 3) & 1) * 8 + (l & 7);   // within m16 frag
    const int a_chk_off = (l >> 4);                       // 0/1 -> k8 half
    const int b_row_off = ((l >> 4) & 1) * 8 + (l & 7);   // within n16 pair
    const int b_chk_off = ((l >> 3) & 1);                 // k8 half

    for (int ch = 0; ch < NCHUNK; ch++) {
        __syncthreads();
        const float* Xc = Xp + ch * BKC;
        const float* Wc = Wp + ch * BKC;
        // load + split-convert: 128x64 fp32 -> bf16 hi/lo, swizzled
#pragma unroll
        for (int it = 0; it < 16; it++) {
            int idx = tid + it * 256;
            int r = idx >> 5, c2 = idx & 31;      // float2 col
            uint32_t off = swz(r, c2 >> 2) + ((c2 & 3) << 2);
            uint32_t hp, lp;
            split2(*(const float2*)(Xc + (size_t)r * DMODEL + c2 * 2), hp, lp);
            *(uint32_t*)(sAhi + off) = hp;
            *(uint32_t*)(sAlo + off) = lp;
            split2(*(const float2*)(Wc + (size_t)r * DMODEL + c2 * 2), hp, lp);
            *(uint32_t*)(sBhi + off) = hp;
            *(uint32_t*)(sBlo + off) = lp;
        }
        __syncthreads();

#pragma unroll
        for (int ks = 0; ks < 4; ks++) {
            uint32_t ahi[4][4], alo[4][4], bhi[4][2], blo[4][2];
#pragma unroll
            for (int mi = 0; mi < 4; mi++) {
                int row = warp_m + mi * 16 + a_row_off;
                uint32_t o = swz(row, ks * 2 + a_chk_off);
                ldsm_x4(ahi[mi][0], ahi[mi][1], ahi[mi][2], ahi[mi][3], aAhi + o);
                ldsm_x4(alo[mi][0], alo[mi][1], alo[mi][2], alo[mi][3], aAlo + o);
            }
#pragma unroll
            for (int nj = 0; nj < 2; nj++) {     // each x4 covers two n8 frags
                int row = warp_n + nj * 16 + b_row_off;
                uint32_t o = swz(row, ks * 2 + b_chk_off);
                ldsm_x4(bhi[nj*2][0], bhi[nj*2][1], bhi[nj*2+1][0], bhi[nj*2+1][1], aBhi + o);
                ldsm_x4(blo[nj*2][0], blo[nj*2][1], blo[nj*2+1][0], blo[nj*2+1][1], aBlo + o);
            }
#pragma unroll
            for (int mi = 0; mi < 4; mi++)
#pragma unroll
                for (int ni = 0; ni < 4; ni++) {
                    mma_bf16(c[mi][ni], ahi[mi], bhi[ni]);
                    mma_bf16(c[mi][ni], ahi[mi], blo[ni]);
                    mma_bf16(c[mi][ni], alo[mi], bhi[ni]);
                }
        }
    }

    // Epilogue: C frag -> rows m_base+(l>>2)[+8], cols n_base+(l&3)*2..+1
#pragma unroll
    for (int mi = 0; mi < 4; mi++)
#pragma unroll
        for (int ni = 0; ni < 4; ni++) {
            int colg = n0 + warp_n + ni * 8 + (l & 3) * 2;
            float2 bv = *(const float2*)&bias[colg];
            int r0 = m0 + warp_m + mi * 16 + (l >> 2);
#pragma unroll
            for (int half = 0; half < 2; half++) {
                int m = r0 + half * 8;
                float2 o2;
                o2.x = c[mi][ni][half * 2 + 0] + bv.x;
                o2.y = c[mi][ni][half * 2 + 1] + bv.y;
                if (SPLIT) {
                    int b = m >> 11, srow = m & (SS - 1);
                    int h = colg >> 6, d = colg & (DK - 1);
                    *(float2*)&Y[(((size_t)(b * NHEADS + h)) * SS + srow) * DK + d] = o2;
                } else {
                    *(float2*)&Y[(size_t)m * DMODEL + colg] = o2;
                }
            }
        }
}

__global__ __launch_bounds__(256) void gemm_qkv_tc(
    const float* __restrict__ q,  const float* __restrict__ k,  const float* __restrict__ v,
    const float* __restrict__ Wq, const float* __restrict__ Wk, const float* __restrict__ Wv,
    const float* __restrict__ bq, const float* __restrict__ bk, const float* __restrict__ bv)
{
    int z = blockIdx.z;
    const float* X    = (z == 0) ? q  : (z == 1) ? k  : v;
    const float* W    = (z == 0) ? Wq : (z == 1) ? Wk : Wv;
    const float* bias = (z == 0) ? bq : (z == 1) ? bk : bv;
    float*       Y    = (z == 0) ? g_Q : (z == 1) ? g_K : g_V;
    gemm_tc_body<true>(X, W, bias, Y);
}

__global__ __launch_bounds__(256) void gemm_out_tc(
    const float* __restrict__ Wo, const float* __restrict__ bo, float* __restrict__ out)
{
    gemm_tc_body<false>(g_C, Wo, bo, out);
}

// ---------------------------------------------------------------------------
// Flash attention, fp32, causal (unchanged — proven at rel_err 5.7e-7).
// ---------------------------------------------------------------------------
#define ATTN_SMEM ((64*68*2 + 64*64) * 4)

__global__ __launch_bounds__(256) void attn_kernel()
{
    extern __shared__ float smf[];
    float* Qs = smf;                 // Qs[d*68 + r]   (transposed)
    float* KP = smf + 64*68;         // K^T[d*68+c] then P[r*68+c]
    float* Vs = KP + 64*68;          // V[j*64 + d]

    const int tid = threadIdx.x;
    const int tx = tid & 15, ty = tid >> 4;
    const int qt = (int)gridDim.x - 1 - (int)blockIdx.x;   // heavy tiles first
    const int bh = blockIdx.y;

    const float* Qg  = g_Q + (size_t)bh * SS * DK + (size_t)qt * 64 * DK;
    const float* Kg0 = g_K + (size_t)bh * SS * DK;
    const float* Vg0 = g_V + (size_t)bh * SS * DK;

#pragma unroll
    for (int ll = 0; ll < 4; ll++) {
        int idx = tid + ll * 256;
        int r = idx & 63, c4 = (idx >> 6) * 4;
        float4 a = *(const float4*)&Qg[r * DK + c4];
        Qs[(c4+0)*68 + r] = a.x; Qs[(c4+1)*68 + r] = a.y;
        Qs[(c4+2)*68 + r] = a.z; Qs[(c4+3)*68 + r] = a.w;
    }

    float m_run[4], l_run[4], o[4][4];
#pragma unroll
    for (int i = 0; i < 4; i++) {
        m_run[i] = -INFINITY; l_run[i] = 0.f;
#pragma unroll
        for (int j = 0; j < 4; j++) o[i][j] = 0.f;
    }

    const float scale = 0.125f;   // 1/sqrt(64)

    for (int kt = 0; kt <= qt; kt++) {
        const float* Kg = Kg0 + (size_t)kt * 64 * DK;
        const float* Vg = Vg0 + (size_t)kt * 64 * DK;

        __syncthreads();
#pragma unroll
        for (int ll = 0; ll < 4; ll++) {
            int idx = tid + ll * 256;
            int r = idx & 63, c4 = (idx >> 6) * 4;
            float4 a = *(const float4*)&Kg[r * DK + c4];
            KP[(c4+0)*68 + r] = a.x; KP[(c4+1)*68 + r] = a.y;
            KP[(c4+2)*68 + r] = a.z; KP[(c4+3)*68 + r] = a.w;
            int r2 = idx >> 4, c42 = (idx & 15) * 4;
            *(float4*)&Vs[r2 * 64 + c42] = *(const float4*)&Vg[r2 * DK + c42];
        }
        __syncthreads();

        float s[4][4];
#pragma unroll
        for (int i = 0; i < 4; i++)
#pragma unroll
            for (int j = 0; j < 4; j++) s[i][j] = 0.f;
#pragma unroll 16
        for (int d = 0; d < 64; d++) {
            float a[4], b[4];
            *(float4*)a = *(const float4*)&Qs[d*68 + ty*4];
            *(float4*)b = *(const float4*)&KP[d*68 + tx*4];
#pragma unroll
            for (int i = 0; i < 4; i++)
#pragma unroll
                for (int j = 0; j < 4; j++)
                    s[i][j] = fmaf(a[i], b[j], s[i][j]);
        }

        if (kt == qt) {
#pragma unroll
            for (int i = 0; i < 4; i++)
#pragma unroll
                for (int j = 0; j < 4; j++) {
                    int qi = ty*4 + i, kj = tx*4 + j;
                    s[i][j] = (kj <= qi) ? s[i][j] * scale : -INFINITY;
                }
        } else {
#pragma unroll
            for (int i = 0; i < 4; i++)
#pragma unroll
                for (int j = 0; j < 4; j++) s[i][j] *= scale;
        }

        float rmax[4];
#pragma unroll
        for (int i = 0; i < 4; i++)
            rmax[i] = fmaxf(fmaxf(s[i][0], s[i][1]), fmaxf(s[i][2], s[i][3]));
#pragma unroll
        for (int off = 8; off >= 1; off >>= 1)
#pragma unroll
            for (int i = 0; i < 4; i++)
                rmax[i] = fmaxf(rmax[i], __shfl_xor_sync(0xffffffffu, rmax[i], off));

        float corr[4], rsum[4];
#pragma unroll
        for (int i = 0; i < 4; i++) {
            float mn = fmaxf(m_run[i], rmax[i]);
            corr[i] = __expf(m_run[i] - mn);
            m_run[i] = mn;
            rsum[i] = 0.f;
        }
#pragma unroll
        for (int i = 0; i < 4; i++)
#pragma unroll
            for (int j = 0; j < 4; j++) {
                float p = __expf(s[i][j] - m_run[i]);
                s[i][j] = p;
                rsum[i] += p;
            }
#pragma unroll
        for (int off = 8; off >= 1; off >>= 1)
#pragma unroll
            for (int i = 0; i < 4; i++)
                rsum[i] += __shfl_xor_sync(0xffffffffu, rsum[i], off);
#pragma unroll
        for (int i = 0; i < 4; i++) {
            l_run[i] = l_run[i] * corr[i] + rsum[i];
#pragma unroll
            for (int j = 0; j < 4; j++) o[i][j] *= corr[i];
        }

        __syncthreads();
#pragma unroll
        for (int i = 0; i < 4; i++) {
            float4 pv; pv.x = s[i][0]; pv.y = s[i][1]; pv.z = s[i][2]; pv.w = s[i][3];
            *(float4*)&KP[(ty*4 + i)*68 + tx*4] = pv;
        }
        __syncthreads();

#pragma unroll 16
        for (int jj = 0; jj < 64; jj++) {
            float4 b4 = *(const float4*)&Vs[jj*64 + tx*4];
            float a0 = KP[(ty*4+0)*68 + jj];
            float a1 = KP[(ty*4+1)*68 + jj];
            float a2 = KP[(ty*4+2)*68 + jj];
            float a3 = KP[(ty*4+3)*68 + jj];
            o[0][0] = fmaf(a0, b4.x, o[0][0]); o[0][1] = fmaf(a0, b4.y, o[0][1]);
            o[0][2] = fmaf(a0, b4.z, o[0][2]); o[0][3] = fmaf(a0, b4.w, o[0][3]);
            o[1][0] = fmaf(a1, b4.x, o[1][0]); o[1][1] = fmaf(a1, b4.y, o[1][1]);
            o[1][2] = fmaf(a1, b4.z, o[1][2]); o[1][3] = fmaf(a1, b4.w, o[1][3]);
            o[2][0] = fmaf(a2, b4.x, o[2][0]); o[2][1] = fmaf(a2, b4.y, o[2][1]);
            o[2][2] = fmaf(a2, b4.z, o[2][2]); o[2][3] = fmaf(a2, b4.w, o[2][3]);
            o[3][0] = fmaf(a3, b4.x, o[3][0]); o[3][1] = fmaf(a3, b4.y, o[3][1]);
            o[3][2] = fmaf(a3, b4.z, o[3][2]); o[3][3] = fmaf(a3, b4.w, o[3][3]);
        }
    }

    int b = bh / NHEADS, h = bh % NHEADS;
#pragma unroll
    for (int i = 0; i < 4; i++) {
        float inv = 1.f / l_run[i];
        int srow = qt*64 + ty*4 + i;
        float4 vv;
        vv.x = o[i][0] * inv; vv.y = o[i][1] * inv;
        vv.z = o[i][2] * inv; vv.w = o[i][3] * inv;
        *(float4*)&g_C[((size_t)(b * SS + srow)) * DMODEL + h * DK + tx*4] = vv;
    }
}

// ---------------------------------------------------------------------------

extern "C" void kernel_launch(void* const* d_in, const int* in_sizes, int n_in,
                              void* d_out, int out_size)
{
    const float* q  = (const float*)d_in[0];
    const float* k  = (const float*)d_in[1];
    const float* v  = (const float*)d_in[2];
    const float* Wq = (const float*)d_in[3];
    const float* bq = (const float*)d_in[4];
    const float* Wk = (const float*)d_in[5];
    const float* bk = (const float*)d_in[6];
    const float* Wv = (const float*)d_in[7];
    const float* bv = (const float*)d_in[8];
    const float* Wo = (const float*)d_in[9];
    const float* bo = (const float*)d_in[10];
    // d_in[11] = mask (exact tril; handled as causal structure in-kernel)

    float* out = (float*)d_out;

    cudaFuncSetAttribute(gemm_qkv_tc, cudaFuncAttributeMaxDynamicSharedMemorySize, GEMM_SMEM);
    cudaFuncSetAttribute(gemm_out_tc, cudaFuncAttributeMaxDynamicSharedMemorySize, GEMM_SMEM);
    cudaFuncSetAttribute(attn_kernel, cudaFuncAttributeMaxDynamicSharedMemorySize, ATTN_SMEM);

    // 1) QKV projections (mma.sync split-bf16, head-split output layout)
    gemm_qkv_tc<<<dim3(DMODEL/128, NTOK/128, 3), 256, GEMM_SMEM>>>(
        q, k, v, Wq, Wk, Wv, bq, bk, bv);

    // 2) Flash attention (causal, fp32)
    attn_kernel<<<dim3(SS/64, BB*NHEADS), 256, ATTN_SMEM>>>();

    // 3) Output projection straight into d_out
    gemm_out_tc<<<dim3(DMODEL/128, NTOK/128), 256, GEMM_SMEM>>>(Wo, bo, out);
}

// round 8
// speedup vs baseline: 2.6548x; 1.7153x over previous
#include <cuda_runtime.h>
#include <cuda_bf16.h>
#include <math.h>
#include <stdint.h>

#define DMODEL 1024
#define NHEADS 16
#define DK 64
#define BB 2
#define SS 2048
#define NTOK (BB*SS)

// Scratch (allocation-free rule: __device__ globals).
__device__ float g_Q[NTOK*DMODEL];   // [B*H, S, DK] head-major
__device__ float g_K[NTOK*DMODEL];   // [B*H, S, DK]
__device__ float g_V[NTOK*DMODEL];   // [B*H, S, DK]
__device__ float g_C[NTOK*DMODEL];   // [B, S, H*DK] token-major (for out-proj)

// ===========================================================================
// Warp-level tensor core helpers (legacy mma.sync path — works on compute_103)
// ===========================================================================
__device__ __forceinline__ uint32_t smem_u32(const void* p) {
    uint32_t a;
    asm("{ .reg .u64 t; cvta.to.shared.u64 t, %1; cvt.u32.u64 %0, t; }"
        : "=r"(a) : "l"(p));
    return a;
}

__device__ __forceinline__ void ldsm_x4(uint32_t& r0, uint32_t& r1,
                                        uint32_t& r2, uint32_t& r3, uint32_t addr) {
    asm volatile("ldmatrix.sync.aligned.m8n8.x4.shared.b16 {%0,%1,%2,%3}, [%4];"
                 : "=r"(r0), "=r"(r1), "=r"(r2), "=r"(r3) : "r"(addr));
}

__device__ __forceinline__ void ldsm_x4_t(uint32_t& r0, uint32_t& r1,
                                          uint32_t& r2, uint32_t& r3, uint32_t addr) {
    asm volatile("ldmatrix.sync.aligned.m8n8.x4.trans.shared.b16 {%0,%1,%2,%3}, [%4];"
                 : "=r"(r0), "=r"(r1), "=r"(r2), "=r"(r3) : "r"(addr));
}

__device__ __forceinline__ void mma_bf16(float* c, const uint32_t* a, const uint32_t* b) {
    asm volatile(
        "mma.sync.aligned.m16n8k16.row.col.f32.bf16.bf16.f32 "
        "{%0,%1,%2,%3}, {%4,%5,%6,%7}, {%8,%9}, {%0,%1,%2,%3};"
        : "+f"(c[0]), "+f"(c[1]), "+f"(c[2]), "+f"(c[3])
        : "r"(a[0]), "r"(a[1]), "r"(a[2]), "r"(a[3]), "r"(b[0]), "r"(b[1]));
}

// split fp32 -> (hi, lo) bf16x2 packs for two consecutive values
__device__ __forceinline__ void split2(float2 v, uint32_t& hp, uint32_t& lp) {
    asm("cvt.rn.bf16x2.f32 %0, %1, %2;" : "=r"(hp) : "f"(v.y), "f"(v.x));
    float h0 = __uint_as_float(hp << 16);
    float h1 = __uint_as_float(hp & 0xffff0000u);
    asm("cvt.rn.bf16x2.f32 %0, %1, %2;" : "=r"(lp) : "f"(v.y - h1), "f"(v.x - h0));
}

__device__ __forceinline__ uint32_t swz(int row, int chunk) {
    return (uint32_t)(row * 128 + ((chunk ^ (row & 7)) << 4));
}

// ===========================================================================
// Tensor-core GEMM: Y = X @ W^T + b  (split-bf16: hi*hi + hi*lo + lo*hi)
// CTA tile 128x128, BK=64, 256 threads (8 warps, 2m x 4n), warp tile 64x32.
// ===========================================================================
#define BKC 64
#define NCHUNK (DMODEL / BKC)        // 16
#define TILE_B (128 * BKC * 2)       // 16 KB per bf16 tile
#define GEMM_SMEM (4 * TILE_B)       // 64 KB

template<bool SPLIT>
__device__ __forceinline__ void gemm_tc_body(const float* __restrict__ X,
                                             const float* __restrict__ W,
                                             const float* __restrict__ bias,
                                             float* __restrict__ Y)
{
    extern __shared__ char smc[];
    char* sAhi = smc;
    char* sAlo = smc + TILE_B;
    char* sBhi = smc + 2 * TILE_B;
    char* sBlo = smc + 3 * TILE_B;
    const uint32_t aAhi = smem_u32(sAhi), aAlo = smem_u32(sAlo);
    const uint32_t aBhi = smem_u32(sBhi), aBlo = smem_u32(sBlo);

    const int tid = threadIdx.x;
    const int wid = tid >> 5, l = tid & 31;
    const int warp_m = (wid & 1) * 64;
    const int warp_n = (wid >> 1) * 32;
    const int m0 = blockIdx.y * 128, n0 = blockIdx.x * 128;

    float c[4][4][4];
#pragma unroll
    for (int i = 0; i < 4; i++)
#pragma unroll
        for (int j = 0; j < 4; j++)
#pragma unroll
            for (int t = 0; t < 4; t++) c[i][j][t] = 0.f;

    const float* Xp = X + (size_t)m0 * DMODEL;
    const float* Wp = W + (size_t)n0 * DMODEL;

    const int a_row_off = ((l >> 3) & 1) * 8 + (l & 7);
    const int a_chk_off = (l >> 4);
    const int b_row_off = ((l >> 4) & 1) * 8 + (l & 7);
    const int b_chk_off = ((l >> 3) & 1);

    for (int ch = 0; ch < NCHUNK; ch++) {
        __syncthreads();
        const float* Xc = Xp + ch * BKC;
        const float* Wc = Wp + ch * BKC;
#pragma unroll
        for (int it = 0; it < 16; it++) {
            int idx = tid + it * 256;
            int r = idx >> 5, c2 = idx & 31;
            uint32_t off = swz(r, c2 >> 2) + ((c2 & 3) << 2);
            uint32_t hp, lp;
            split2(*(const float2*)(Xc + (size_t)r * DMODEL + c2 * 2), hp, lp);
            *(uint32_t*)(sAhi + off) = hp;
            *(uint32_t*)(sAlo + off) = lp;
            split2(*(const float2*)(Wc + (size_t)r * DMODEL + c2 * 2), hp, lp);
            *(uint32_t*)(sBhi + off) = hp;
            *(uint32_t*)(sBlo + off) = lp;
        }
        __syncthreads();

#pragma unroll
        for (int ks = 0; ks < 4; ks++) {
            uint32_t ahi[4][4], alo[4][4], bhi[4][2], blo[4][2];
#pragma unroll
            for (int mi = 0; mi < 4; mi++) {
                int row = warp_m + mi * 16 + a_row_off;
                uint32_t o = swz(row, ks * 2 + a_chk_off);
                ldsm_x4(ahi[mi][0], ahi[mi][1], ahi[mi][2], ahi[mi][3], aAhi + o);
                ldsm_x4(alo[mi][0], alo[mi][1], alo[mi][2], alo[mi][3], aAlo + o);
            }
#pragma unroll
            for (int nj = 0; nj < 2; nj++) {
                int row = warp_n + nj * 16 + b_row_off;
                uint32_t o = swz(row, ks * 2 + b_chk_off);
                ldsm_x4(bhi[nj*2][0], bhi[nj*2][1], bhi[nj*2+1][0], bhi[nj*2+1][1], aBhi + o);
                ldsm_x4(blo[nj*2][0], blo[nj*2][1], blo[nj*2+1][0], blo[nj*2+1][1], aBlo + o);
            }
#pragma unroll
            for (int mi = 0; mi < 4; mi++)
#pragma unroll
                for (int ni = 0; ni < 4; ni++) {
                    mma_bf16(c[mi][ni], ahi[mi], bhi[ni]);
                    mma_bf16(c[mi][ni], ahi[mi], blo[ni]);
                    mma_bf16(c[mi][ni], alo[mi], bhi[ni]);
                }
        }
    }

#pragma unroll
    for (int mi = 0; mi < 4; mi++)
#pragma unroll
        for (int ni = 0; ni < 4; ni++) {
            int colg = n0 + warp_n + ni * 8 + (l & 3) * 2;
            float2 bv = *(const float2*)&bias[colg];
            int r0 = m0 + warp_m + mi * 16 + (l >> 2);
#pragma unroll
            for (int half = 0; half < 2; half++) {
                int m = r0 + half * 8;
                float2 o2;
                o2.x = c[mi][ni][half * 2 + 0] + bv.x;
                o2.y = c[mi][ni][half * 2 + 1] + bv.y;
                if (SPLIT) {
                    int b = m >> 11, srow = m & (SS - 1);
                    int h = colg >> 6, d = colg & (DK - 1);
                    *(float2*)&Y[(((size_t)(b * NHEADS + h)) * SS + srow) * DK + d] = o2;
                } else {
                    *(float2*)&Y[(size_t)m * DMODEL + colg] = o2;
                }
            }
        }
}

__global__ __launch_bounds__(256) void gemm_qkv_tc(
    const float* __restrict__ q,  const float* __restrict__ k,  const float* __restrict__ v,
    const float* __restrict__ Wq, const float* __restrict__ Wk, const float* __restrict__ Wv,
    const float* __restrict__ bq, const float* __restrict__ bk, const float* __restrict__ bv)
{
    int z = blockIdx.z;
    const float* X    = (z == 0) ? q  : (z == 1) ? k  : v;
    const float* W    = (z == 0) ? Wq : (z == 1) ? Wk : Wv;
    const float* bias = (z == 0) ? bq : (z == 1) ? bk : bv;
    float*       Y    = (z == 0) ? g_Q : (z == 1) ? g_K : g_V;
    gemm_tc_body<true>(X, W, bias, Y);
}

__global__ __launch_bounds__(256) void gemm_out_tc(
    const float* __restrict__ Wo, const float* __restrict__ bo, float* __restrict__ out)
{
    gemm_tc_body<false>(g_C, Wo, bo, out);
}

// ===========================================================================
// Flash attention via mma.sync split-bf16. CTA = 128 q-rows x 64-key tiles,
// 8 warps x 16 rows (FA2 style). Causal; softmax fp32 in registers.
// Smem: Qhi/Qlo 16K each, Khi/Klo 8K each, Vhi/Vlo 8K each = 64 KB.
// ===========================================================================
#define ATTN_SMEM (64 * 1024)

__global__ __launch_bounds__(256) void attn_tc_kernel()
{
    extern __shared__ char sma[];
    char* sQh = sma;
    char* sQl = sma + 16384;
    char* sKh = sma + 32768;
    char* sKl = sma + 40960;
    char* sVh = sma + 49152;
    char* sVl = sma + 57344;
    const uint32_t aQh = smem_u32(sQh), aQl = smem_u32(sQl);
    const uint32_t aKh = smem_u32(sKh), aKl = smem_u32(sKl);
    const uint32_t aVh = smem_u32(sVh), aVl = smem_u32(sVl);

    const int tid = threadIdx.x;
    const int wid = tid >> 5, l = tid & 31;
    const int t  = (int)gridDim.x - 1 - (int)blockIdx.x;   // heavy tiles first
    const int bh = blockIdx.y;
    const int m0 = t * 128;

    const float* Qg  = g_Q + (size_t)bh * SS * DK + (size_t)m0 * DK;
    const float* Kg0 = g_K + (size_t)bh * SS * DK;
    const float* Vg0 = g_V + (size_t)bh * SS * DK;

    // ldmatrix lane-address components
    const int a_row_off = ((l >> 3) & 1) * 8 + (l & 7);
    const int a_chk_off = (l >> 4);
    const int b_row_off = ((l >> 4) & 1) * 8 + (l & 7);
    const int b_chk_off = ((l >> 3) & 1);
    const int v_row_off = ((l >> 3) & 1) * 8 + (l & 7);
    const int v_chk_off = (l >> 4);

    // ---- load Q (scaled by 1/sqrt(dk)), split hi/lo into smem ----
#pragma unroll
    for (int it = 0; it < 16; it++) {
        int idx = tid + it * 256;
        int r = idx >> 5, c2 = idx & 31;
        float2 v = *(const float2*)(Qg + (size_t)r * DK + c2 * 2);
        v.x *= 0.125f; v.y *= 0.125f;
        uint32_t hp, lp;
        split2(v, hp, lp);
        uint32_t off = swz(r, c2 >> 2) + ((c2 & 3) << 2);
        *(uint32_t*)(sQh + off) = hp;
        *(uint32_t*)(sQl + off) = lp;
    }
    __syncthreads();

    // ---- Q A-frags held in registers for the whole kernel ----
    uint32_t qh[4][4], ql[4][4];
#pragma unroll
    for (int ks = 0; ks < 4; ks++) {
        uint32_t o = swz(wid * 16 + a_row_off, ks * 2 + a_chk_off);
        ldsm_x4(qh[ks][0], qh[ks][1], qh[ks][2], qh[ks][3], aQh + o);
        ldsm_x4(ql[ks][0], ql[ks][1], ql[ks][2], ql[ks][3], aQl + o);
    }

    float o[8][4];
#pragma unroll
    for (int ng = 0; ng < 8; ng++)
#pragma unroll
        for (int i = 0; i < 4; i++) o[ng][i] = 0.f;
    float mA = -INFINITY, mB = -INFINITY, lA = 0.f, lB = 0.f;

    const int rowA = m0 + wid * 16 + (l >> 2);
    const int rowB = rowA + 8;
    const int kmax = 2 * t + 1;

    for (int kt = 0; kt <= kmax; kt++) {
        const float* Kg = Kg0 + (size_t)kt * 64 * DK;
        const float* Vg = Vg0 + (size_t)kt * 64 * DK;

        if (kt) __syncthreads();    // previous iter's ldmatrix reads done
#pragma unroll
        for (int it = 0; it < 8; it++) {
            int idx = tid + it * 256;
            int r = idx >> 5, c2 = idx & 31;
            uint32_t off = swz(r, c2 >> 2) + ((c2 & 3) << 2);
            uint32_t hp, lp;
            split2(*(const float2*)(Kg + (size_t)r * DK + c2 * 2), hp, lp);
            *(uint32_t*)(sKh + off) = hp;
            *(uint32_t*)(sKl + off) = lp;
            split2(*(const float2*)(Vg + (size_t)r * DK + c2 * 2), hp, lp);
            *(uint32_t*)(sVh + off) = hp;
            *(uint32_t*)(sVl + off) = lp;
        }
        __syncthreads();

        // ---- S = Q K^T (3-split) ----
        float s[8][4];
#pragma unroll
        for (int ng = 0; ng < 8; ng++)
#pragma unroll
            for (int i = 0; i < 4; i++) s[ng][i] = 0.f;
#pragma unroll
        for (int ks = 0; ks < 4; ks++) {
            uint32_t kbh[8][2], kbl[8][2];
#pragma unroll
            for (int g2 = 0; g2 < 4; g2++) {
                uint32_t off = swz(g2 * 16 + b_row_off, ks * 2 + b_chk_off);
                ldsm_x4(kbh[g2*2][0], kbh[g2*2][1], kbh[g2*2+1][0], kbh[g2*2+1][1], aKh + off);
                ldsm_x4(kbl[g2*2][0], kbl[g2*2][1], kbl[g2*2+1][0], kbl[g2*2+1][1], aKl + off);
            }
#pragma unroll
            for (int ng = 0; ng < 8; ng++) {
                mma_bf16(s[ng], qh[ks], kbh[ng]);
                mma_bf16(s[ng], qh[ks], kbl[ng]);
                mma_bf16(s[ng], ql[ks], kbh[ng]);
            }
        }

        // ---- causal mask (only possible on the last two k-tiles) ----
        if (kt >= 2 * t) {
#pragma unroll
            for (int ng = 0; ng < 8; ng++) {
                int cb = kt * 64 + ng * 8 + (l & 3) * 2;
                if (cb     > rowA) s[ng][0] = -INFINITY;
                if (cb + 1 > rowA) s[ng][1] = -INFINITY;
                if (cb     > rowB) s[ng][2] = -INFINITY;
                if (cb + 1 > rowB) s[ng][3] = -INFINITY;
            }
        }

        // ---- online softmax (row reductions inside lane quad) ----
        float mxA = -INFINITY, mxB = -INFINITY;
#pragma unroll
        for (int ng = 0; ng < 8; ng++) {
            mxA = fmaxf(mxA, fmaxf(s[ng][0], s[ng][1]));
            mxB = fmaxf(mxB, fmaxf(s[ng][2], s[ng][3]));
        }
#pragma unroll
        for (int off = 1; off <= 2; off <<= 1) {
            mxA = fmaxf(mxA, __shfl_xor_sync(0xffffffffu, mxA, off));
            mxB = fmaxf(mxB, __shfl_xor_sync(0xffffffffu, mxB, off));
        }
        float mnA = fmaxf(mA, mxA), mnB = fmaxf(mB, mxB);
        float corrA = __expf(mA - mnA), corrB = __expf(mB - mnB);
        mA = mnA; mB = mnB;

        float suA = 0.f, suB = 0.f;
#pragma unroll
        for (int ng = 0; ng < 8; ng++) {
            s[ng][0] = __expf(s[ng][0] - mA);
            s[ng][1] = __expf(s[ng][1] - mA);
            s[ng][2] = __expf(s[ng][2] - mB);
            s[ng][3] = __expf(s[ng][3] - mB);
            suA += s[ng][0] + s[ng][1];
            suB += s[ng][2] + s[ng][3];
        }
#pragma unroll
        for (int off = 1; off <= 2; off <<= 1) {
            suA += __shfl_xor_sync(0xffffffffu, suA, off);
            suB += __shfl_xor_sync(0xffffffffu, suB, off);
        }
        lA = lA * corrA + suA;
        lB = lB * corrB + suB;
#pragma unroll
        for (int ng = 0; ng < 8; ng++) {
            o[ng][0] *= corrA; o[ng][1] *= corrA;
            o[ng][2] *= corrB; o[ng][3] *= corrB;
        }

        // ---- pack P into A-frag layout (C-frag -> A-frag, in registers) ----
        uint32_t ph[4][4], pl[4][4];
#pragma unroll
        for (int kk = 0; kk < 4; kk++) {
            split2(make_float2(s[2*kk  ][0], s[2*kk  ][1]), ph[kk][0], pl[kk][0]);
            split2(make_float2(s[2*kk  ][2], s[2*kk  ][3]), ph[kk][1], pl[kk][1]);
            split2(make_float2(s[2*kk+1][0], s[2*kk+1][1]), ph[kk][2], pl[kk][2]);
            split2(make_float2(s[2*kk+1][2], s[2*kk+1][3]), ph[kk][3], pl[kk][3]);
        }

        // ---- O += P V (3-split, V via ldmatrix.trans) ----
#pragma unroll
        for (int kk = 0; kk < 4; kk++) {
            uint32_t vbh[8][2], vbl[8][2];
#pragma unroll
            for (int g2 = 0; g2 < 4; g2++) {
                uint32_t off = swz(kk * 16 + v_row_off, g2 * 2 + v_chk_off);
                ldsm_x4_t(vbh[g2*2][0], vbh[g2*2][1], vbh[g2*2+1][0], vbh[g2*2+1][1], aVh + off);
                ldsm_x4_t(vbl[g2*2][0], vbl[g2*2][1], vbl[g2*2+1][0], vbl[g2*2+1][1], aVl + off);
            }
#pragma unroll
            for (int ng = 0; ng < 8; ng++) {
                mma_bf16(o[ng], ph[kk], vbh[ng]);
                mma_bf16(o[ng], ph[kk], vbl[ng]);
                mma_bf16(o[ng], pl[kk], vbh[ng]);
            }
        }
    }

    // ---- epilogue: normalize, write ctx token-major [B, S, H*DK] ----
    const float invA = 1.f / lA, invB = 1.f / lB;
    const int b = bh / NHEADS, h = bh % NHEADS;
    float* dstA = &g_C[((size_t)(b * SS + rowA)) * DMODEL + h * DK];
    float* dstB = &g_C[((size_t)(b * SS + rowB)) * DMODEL + h * DK];
#pragma unroll
    for (int ng = 0; ng < 8; ng++) {
        int col = ng * 8 + (l & 3) * 2;
        float2 wa; wa.x = o[ng][0] * invA; wa.y = o[ng][1] * invA;
        float2 wb; wb.x = o[ng][2] * invB; wb.y = o[ng][3] * invB;
        *(float2*)(dstA + col) = wa;
        *(float2*)(dstB + col) = wb;
    }
}

// ---------------------------------------------------------------------------

extern "C" void kernel_launch(void* const* d_in, const int* in_sizes, int n_in,
                              void* d_out, int out_size)
{
    const float* q  = (const float*)d_in[0];
    const float* k  = (const float*)d_in[1];
    const float* v  = (const float*)d_in[2];
    const float* Wq = (const float*)d_in[3];
    const float* bq = (const float*)d_in[4];
    const float* Wk = (const float*)d_in[5];
    const float* bk = (const float*)d_in[6];
    const float* Wv = (const float*)d_in[7];
    const float* bv = (const float*)d_in[8];
    const float* Wo = (const float*)d_in[9];
    const float* bo = (const float*)d_in[10];
    // d_in[11] = mask (exact tril; handled as causal structure in-kernel)

    float* out = (float*)d_out;

    cudaFuncSetAttribute(gemm_qkv_tc,    cudaFuncAttributeMaxDynamicSharedMemorySize, GEMM_SMEM);
    cudaFuncSetAttribute(gemm_out_tc,    cudaFuncAttributeMaxDynamicSharedMemorySize, GEMM_SMEM);
    cudaFuncSetAttribute(attn_tc_kernel, cudaFuncAttributeMaxDynamicSharedMemorySize, ATTN_SMEM);

    // 1) QKV projections (mma.sync split-bf16, head-split output layout)
    gemm_qkv_tc<<<dim3(DMODEL/128, NTOK/128, 3), 256, GEMM_SMEM>>>(
        q, k, v, Wq, Wk, Wv, bq, bk, bv);

    // 2) Flash attention (causal, mma.sync split-bf16)
    attn_tc_kernel<<<dim3(SS/128, BB*NHEADS), 256, ATTN_SMEM>>>();

    // 3) Output projection straight into d_out
    gemm_out_tc<<<dim3(DMODEL/128, NTOK/128), 256, GEMM_SMEM>>>(Wo, bo, out);
}